// round 15
// baseline (speedup 1.0000x reference)
#include <cuda_runtime.h>
#include <cuda_bf16.h>

// R12 = R11 with (a) trivial setup node: the E exponent table is generated by
// a DETERMINISTIC DFS in the reference, so the scatter layer->canonical-lex
// coefficient slots is a fixed permutation, hardcoded here (verified to be a
// bijection of 0..54). Setup = 69 gather-stores, no decode loops, no E reads.
// (b) main kernel evaluates both rows in ONE interleaved pass so each
// constant-bank read feeds two FMAs.
// cC layout: [0:5) c1, [5:20) c2 lex, [20:55) c3 lex (i<=j<=k),
//            [55:60) ctc, [60:65) cts, [65] w0, [66] w1, [67] e0, [68] e1.

#define NBLK 1036            // 148 SMs * 7 CTAs
#define NTHR 128
#define TOTT (NBLK * NTHR)   // 132608 row-pairs per iteration

__constant__ float cC[69];

// Canonical-lex slot -> layer index (DFS order of _gen_exponents(5,3)).
__device__ const int kPerm[65] = {
    // c1: v0..v4
    0, 21, 36, 46, 52,
    // c2: (0,0)(0,1)(0,2)(0,3)(0,4)(1,1)(1,2)(1,3)(1,4)(2,2)(2,3)(2,4)(3,3)(3,4)(4,4)
    1, 7, 12, 16, 19, 22, 27, 31, 34, 37, 41, 44, 47, 50, 53,
    // c3 lex (i<=j<=k):
    2, 3, 4, 5, 6,       // (0,0,0..4)
    8, 9, 10, 11,        // (0,1,1..4)
    13, 14, 15,          // (0,2,2..4)
    17, 18,              // (0,3,3..4)
    20,                  // (0,4,4)
    23, 24, 25, 26,      // (1,1,1..4)
    28, 29, 30,          // (1,2,2..4)
    32, 33,              // (1,3,3..4)
    35,                  // (1,4,4)
    38, 39, 40,          // (2,2,2..4)
    42, 43,              // (2,3,3..4)
    45,                  // (2,4,4)
    48, 49,              // (3,3,3..4)
    51,                  // (3,4,4)
    54,                  // (4,4,4)
    // trig coefficients ctc, cts (identity)
    55, 56, 57, 58, 59, 60, 61, 62, 63, 64
};

__global__ void ExternalForcesSI_setup_kernel(const float* __restrict__ layer,
                                              const float* __restrict__ omegas,
                                              const float* __restrict__ ef,
                                              float* __restrict__ cdst) {
    int tx = threadIdx.x;
    if (tx < 65)       cdst[tx] = layer[kPerm[tx]];
    else if (tx == 65) cdst[65] = omegas[0];
    else if (tx == 66) cdst[66] = omegas[1];
    else if (tx == 67) cdst[67] = ef[0];
    else if (tx == 68) cdst[68] = ef[1];
}

struct Pair { float a[5]; float b[5]; };

__device__ __forceinline__ void load_pair(const float4* __restrict__ xp,
                                          const float2* __restrict__ tp,
                                          int off, Pair& P) {
    float4 x0 = xp[2 * off];
    float4 x1 = xp[2 * off + 1];
    float2 tt = tp[off];
    P.a[0] = x0.x; P.a[1] = x0.y; P.a[2] = x0.z; P.a[3] = x0.w; P.a[4] = tt.x;
    P.b[0] = x1.x; P.b[1] = x1.y; P.b[2] = x1.z; P.b[3] = x1.w; P.b[4] = tt.y;
}

template<int NITER>
__global__ __launch_bounds__(NTHR, 7)
void ExternalForcesSI_main_kernel(const float4* __restrict__ x,
                                  const float2* __restrict__ t2,
                                  float4* __restrict__ out,
                                  int npairs, int iters_rt) {
    const int tid = blockIdx.x * NTHR + threadIdx.x;
    const int pm1 = npairs - 1;
    const int iters = (NITER > 0) ? NITER : iters_rt;

    const float w0 = cC[65];
    const float w1 = cC[66];
    const float e0 = cC[67];
    const float e1 = cC[68];

    const float4* __restrict__ xp = x + 2 * tid;
    const float2* __restrict__ tp = t2 + tid;
    float4* __restrict__ op = out + tid;

    Pair buf[2];
    if (NITER > 0) load_pair(xp, tp, 0, buf[0]);
    else           load_pair(xp, tp, min(tid, pm1) - tid, buf[0]);

    #pragma unroll
    for (int it = 0; it < iters; it++) {
        const int cur = it & 1;
        const int nxt = cur ^ 1;

        // ---- prefetch next pair FIRST (LDGs fly during compute) ----
        if (it + 1 < iters) {
            if (NITER > 0 && it + 2 < iters) {
                load_pair(xp, tp, (it + 1) * TOTT, buf[nxt]);   // in-bounds
            } else {
                int pc = min(tid + (it + 1) * TOTT, pm1) - tid;
                load_pair(xp, tp, pc, buf[nxt]);
            }
        }

        const float* va = buf[cur].a;
        const float* vb = buf[cur].b;

        // ---- trig: issue all 20 MUFUs early, fold immediately (both rows
        //      share each coefficient read) ----
        float trigA, trigB;
        {
            float ca = 0.f, sa = 0.f, cb = 0.f, sb = 0.f;
            #pragma unroll
            for (int j = 0; j < 5; j++) {
                float cc = cC[55 + j];
                float ss = cC[60 + j];
                ca = fmaf(cc, __cosf(w0 * va[j]), ca);
                cb = fmaf(cc, __cosf(w0 * vb[j]), cb);
                sa = fmaf(ss, __sinf(w1 * va[j]), sa);
                sb = fmaf(ss, __sinf(w1 * vb[j]), sb);
            }
            trigA = ca + sa;
            trigB = cb + sb;
        }

        // ---- interleaved two-row Horner: each constant read feeds both
        //      rows; A/B chains are independent -> ILP 2 within the nest ----
        float sA, sB;
        {
            float pA[5], pB[5];
            int q2 = 0, q3 = 0;
            #pragma unroll
            for (int i = 0; i < 5; i++) {
                float uiA = cC[i], uiB = uiA;
                #pragma unroll
                for (int j = i; j < 5; j++) {
                    float c2v = cC[5 + q2]; q2++;
                    float tA = c2v, tB = c2v;
                    #pragma unroll
                    for (int k = j; k < 5; k++) {
                        float c3v = cC[20 + q3]; q3++;
                        tA = fmaf(va[k], c3v, tA);
                        tB = fmaf(vb[k], c3v, tB);
                    }
                    uiA = fmaf(va[j], tA, uiA);
                    uiB = fmaf(vb[j], tB, uiB);
                }
                pA[i] = va[i] * uiA;
                pB[i] = vb[i] * uiB;
            }
            sA = (((pA[0] + pA[1]) + (pA[2] + pA[3])) + pA[4]) + trigA;
            sB = (((pB[0] + pB[1]) + (pB[2] + pB[3])) + pB[4]) + trigB;
        }

        float4 res = make_float4(sA * e0, sA * e1, sB * e0, sB * e1);
        if (NITER > 0 && it + 1 < iters) {
            op[it * TOTT] = res;                      // provably in-bounds
        } else {
            if (tid + it * TOTT < npairs) op[it * TOTT] = res;
        }
    }
}

extern "C" void kernel_launch(void* const* d_in, const int* in_sizes, int n_in,
                              void* d_out, int out_size) {
    // metadata order: x, t, layer, omegas, ext_filter, E
    const float4* x      = (const float4*)d_in[0];
    const float2* t2     = (const float2*)d_in[1];
    const float*  layer  = (const float*)d_in[2];
    const float*  omegas = (const float*)d_in[3];
    const float*  ef     = (const float*)d_in[4];
    float4* out = (float4*)d_out;

    const int n = in_sizes[1];        // N_DATA (element count of t), even
    const int npairs = n >> 1;        // 500000
    const int iters = (npairs + TOTT - 1) / TOTT;   // 4 for N=1M

    // Tiny setup: permutation gather into the __constant__ backing store
    // (device address; kernel node, no copy engine).
    static float* cdst = nullptr;     // host-side cache of the symbol address
    if (!cdst) cudaGetSymbolAddress((void**)&cdst, cC);
    ExternalForcesSI_setup_kernel<<<1, 96>>>(layer, omegas, ef, cdst);

    if (iters == 4 && (iters - 1) * TOTT <= npairs) {
        ExternalForcesSI_main_kernel<4><<<NBLK, NTHR>>>(x, t2, out, npairs, iters);
    } else {
        ExternalForcesSI_main_kernel<0><<<NBLK, NTHR>>>(x, t2, out, npairs, iters);
    }
}

// round 16
// speedup vs baseline: 1.4776x; 1.4776x over previous
#include <cuda_runtime.h>
#include <cuda_bf16.h>

// R13 = R11's main kernel EXACTLY (measured 9.60us; R12's interleaved variant
// issued ~55% more instructions and regressed) + R12's trivial permutation
// setup (validated correct) + PDL: the main kernel is launched with
// programmatic stream serialization so the tiny setup node overlaps with its
// launch ramp instead of costing a ~3.4us serialized node gap. Main kernel
// executes cudaGridDependencySynchronize() before reading cC.
// cC layout: [0:5) c1, [5:20) c2 lex, [20:55) c3 lex (i<=j<=k),
//            [55:60) ctc, [60:65) cts, [65] w0, [66] w1, [67] e0, [68] e1.

#define NBLK 1036            // 148 SMs * 7 CTAs
#define NTHR 128
#define TOTT (NBLK * NTHR)   // 132608 row-pairs per iteration

__constant__ float cC[69];

// Canonical-lex slot -> layer index (DFS order of _gen_exponents(5,3));
// verified bijection (R12 passed with identical rel_err).
__device__ const int kPerm[65] = {
    0, 21, 36, 46, 52,
    1, 7, 12, 16, 19, 22, 27, 31, 34, 37, 41, 44, 47, 50, 53,
    2, 3, 4, 5, 6,
    8, 9, 10, 11,
    13, 14, 15,
    17, 18,
    20,
    23, 24, 25, 26,
    28, 29, 30,
    32, 33,
    35,
    38, 39, 40,
    42, 43,
    45,
    48, 49,
    51,
    54,
    55, 56, 57, 58, 59, 60, 61, 62, 63, 64
};

__global__ void ExternalForcesSI_setup_kernel(const float* __restrict__ layer,
                                              const float* __restrict__ omegas,
                                              const float* __restrict__ ef,
                                              float* __restrict__ cdst) {
    int tx = threadIdx.x;
    if (tx < 65)       cdst[tx] = layer[kPerm[tx]];
    else if (tx == 65) cdst[65] = omegas[0];
    else if (tx == 66) cdst[66] = omegas[1];
    else if (tx == 67) cdst[67] = ef[0];
    else if (tx == 68) cdst[68] = ef[1];
}

struct Pair { float a[5]; float b[5]; };

__device__ __forceinline__ void load_pair(const float4* __restrict__ xp,
                                          const float2* __restrict__ tp,
                                          int off, Pair& P) {
    float4 x0 = xp[2 * off];
    float4 x1 = xp[2 * off + 1];
    float2 tt = tp[off];
    P.a[0] = x0.x; P.a[1] = x0.y; P.a[2] = x0.z; P.a[3] = x0.w; P.a[4] = tt.x;
    P.b[0] = x1.x; P.b[1] = x1.y; P.b[2] = x1.z; P.b[3] = x1.w; P.b[4] = tt.y;
}

// Per-row polynomial + trig epilogue, all coefficients from the constant
// bank — EXACT R11 structure (do not interleave: measured slower).
__device__ __forceinline__ float row_eval(const float* v,
                                          const float* C, const float* S) {
    float part[5];
    int q2 = 0, q3 = 0;
    #pragma unroll
    for (int i = 0; i < 5; i++) {
        float ui = cC[i];
        #pragma unroll
        for (int j = i; j < 5; j++) {
            float tij = cC[5 + q2]; q2++;
            #pragma unroll
            for (int k = j; k < 5; k++) {
                tij = fmaf(v[k], cC[20 + q3], tij); q3++;
            }
            ui = fmaf(v[j], tij, ui);
        }
        part[i] = v[i] * ui;
    }
    float a01 = fmaf(cC[55], C[0], cC[56] * C[1]);
    float a23 = fmaf(cC[57], C[2], cC[58] * C[3]);
    float b01 = fmaf(cC[60], S[0], cC[61] * S[1]);
    float b23 = fmaf(cC[62], S[2], cC[63] * S[3]);
    float a4  = fmaf(cC[59], C[4], cC[64] * S[4]);
    return (((part[0] + part[1]) + (part[2] + part[3])) + part[4])
           + (((a01 + a23) + (b01 + b23)) + a4);
}

template<int NITER>
__global__ __launch_bounds__(NTHR, 7)
void ExternalForcesSI_main_kernel(const float4* __restrict__ x,
                                  const float2* __restrict__ t2,
                                  float4* __restrict__ out,
                                  int npairs, int iters_rt) {
#if __CUDA_ARCH__ >= 900
    // PDL: wait until the setup grid's memory is visible before reading cC.
    cudaGridDependencySynchronize();
#endif
    const int tid = blockIdx.x * NTHR + threadIdx.x;
    const int pm1 = npairs - 1;
    const int iters = (NITER > 0) ? NITER : iters_rt;

    const float w0 = cC[65];
    const float w1 = cC[66];
    const float e0 = cC[67];
    const float e1 = cC[68];

    const float4* __restrict__ xp = x + 2 * tid;
    const float2* __restrict__ tp = t2 + tid;
    float4* __restrict__ op = out + tid;

    Pair buf[2];
    if (NITER > 0) load_pair(xp, tp, 0, buf[0]);
    else           load_pair(xp, tp, min(tid, pm1) - tid, buf[0]);

    #pragma unroll
    for (int it = 0; it < iters; it++) {
        const int cur = it & 1;
        const int nxt = cur ^ 1;

        // ---- prefetch next pair FIRST (LDGs fly during compute) ----
        if (it + 1 < iters) {
            if (NITER > 0 && it + 2 < iters) {
                load_pair(xp, tp, (it + 1) * TOTT, buf[nxt]);   // in-bounds
            } else {
                int pc = min(tid + (it + 1) * TOTT, pm1) - tid;
                load_pair(xp, tp, pc, buf[nxt]);
            }
        }

        const float* va = buf[cur].a;
        const float* vb = buf[cur].b;

        // ---- trig: issue all 20 MUFUs early (R11 tree form) ----
        float Ca[5], Sa[5], Cb[5], Sb[5];
        #pragma unroll
        for (int j = 0; j < 5; j++) {
            Ca[j] = __cosf(w0 * va[j]);
            Sa[j] = __sinf(w1 * va[j]);
            Cb[j] = __cosf(w0 * vb[j]);
            Sb[j] = __sinf(w1 * vb[j]);
        }

        float sA = row_eval(va, Ca, Sa);
        float sB = row_eval(vb, Cb, Sb);

        float4 res = make_float4(sA * e0, sA * e1, sB * e0, sB * e1);
        if (NITER > 0 && it + 1 < iters) {
            op[it * TOTT] = res;                      // provably in-bounds
        } else {
            if (tid + it * TOTT < npairs) op[it * TOTT] = res;
        }
    }
}

extern "C" void kernel_launch(void* const* d_in, const int* in_sizes, int n_in,
                              void* d_out, int out_size) {
    // metadata order: x, t, layer, omegas, ext_filter, E
    const float4* x      = (const float4*)d_in[0];
    const float2* t2     = (const float2*)d_in[1];
    const float*  layer  = (const float*)d_in[2];
    const float*  omegas = (const float*)d_in[3];
    const float*  ef     = (const float*)d_in[4];
    float4* out = (float4*)d_out;

    int n = in_sizes[1];              // N_DATA (element count of t), even
    int npairs = n >> 1;              // 500000
    int iters = (npairs + TOTT - 1) / TOTT;   // 4 for N=1M

    // Tiny setup node: permutation gather into the __constant__ backing store.
    static float* cdst = nullptr;     // host-side cache of the symbol address
    if (!cdst) cudaGetSymbolAddress((void**)&cdst, cC);
    ExternalForcesSI_setup_kernel<<<1, 96>>>(layer, omegas, ef, cdst);

    // Main kernel with programmatic stream serialization: overlaps its launch
    // ramp with the setup node; cudaGridDependencySynchronize() inside the
    // kernel provides the ordering.
    cudaLaunchConfig_t cfg = {};
    cfg.gridDim  = dim3(NBLK, 1, 1);
    cfg.blockDim = dim3(NTHR, 1, 1);
    cfg.dynamicSmemBytes = 0;
    cfg.stream = 0;
    cudaLaunchAttribute attrs[1];
    attrs[0].id = cudaLaunchAttributeProgrammaticStreamSerialization;
    attrs[0].val.programmaticStreamSerializationAllowed = 1;
    cfg.attrs = attrs;
    cfg.numAttrs = 1;

    if (iters == 4 && (iters - 1) * TOTT <= npairs) {
        cudaLaunchKernelEx(&cfg, ExternalForcesSI_main_kernel<4>,
                           x, t2, out, npairs, iters);
    } else {
        cudaLaunchKernelEx(&cfg, ExternalForcesSI_main_kernel<0>,
                           x, t2, out, npairs, iters);
    }
}